// round 14
// baseline (speedup 1.0000x reference)
#include <cuda_runtime.h>

#define BB   2
#define CIN  256
#define CMID 64
#define CENC 100
#define HWHW 4096   // 64*64

typedef unsigned long long u64;

// ---- packed fp32x2 helpers (FFMA2: one instr = two fp32 FMAs, full precision)
__device__ __forceinline__ u64 dup2(float v) {
    u64 r; asm("mov.b64 %0, {%1,%1};" : "=l"(r) : "f"(v)); return r;
}
__device__ __forceinline__ void fma2(u64& d, u64 a, u64 b) {
    asm("fma.rn.f32x2 %0, %1, %2, %0;" : "+l"(d) : "l"(a), "l"(b));
}
__device__ __forceinline__ float2 unpack2(u64 v) {
    float2 f; asm("mov.b64 {%0,%1}, %2;" : "=f"(f.x), "=f"(f.y) : "l"(v)); return f;
}

// Scratch (allocation-free rule: __device__ globals)
__device__ float g_W1[BB * CMID * HWHW];        // conv1 output (b,64,64,64)
__device__ float g_W2[BB * CENC * HWHW];        // conv2 output (b,100,64,64)
// softmaxed weights permuted to k4's tile order: [b][tile(64)][within(64)][k(25)][d(4)]
__device__ float g_Wn[BB * 64 * 64 * 100];

// ---------------------------------------------------------------------------
// K1: 1x1 conv (GEMM M=64co x K=256ci x N=4096hw) + BN + ReLU
// block: 64co x 32n, 128 threads, thread = 8co (4 pairs) x 2n, k-chunk 16
// grid (128, 2) = 256 blocks -> every SM occupied.
// per k: 2 A LDS.128 + 1 B LDS.64 + 2 dup + 8 FFMA2
// ---------------------------------------------------------------------------
__global__ __launch_bounds__(128) void k1_conv1x1(
    const float* __restrict__ X, const float* __restrict__ cw,
    const float* __restrict__ gamma, const float* __restrict__ beta,
    const float* __restrict__ mean, const float* __restrict__ var)
{
    __shared__ __align__(16) float As[16][68];   // [k][co]
    __shared__ __align__(16) float Bs[16][36];   // [k][n]
    int b = blockIdx.y;
    int n_base = blockIdx.x * 32;
    int t = threadIdx.x;
    int co0 = (t & 7) * 8;
    int n0  = (t >> 3) * 2;
    const float* Xb = X + (size_t)b * CIN * HWHW;
    u64 acc[4][2];                               // [co-pair][n]
    #pragma unroll
    for (int p = 0; p < 4; ++p) { acc[p][0] = 0ULL; acc[p][1] = 0ULL; }

    for (int kc = 0; kc < CIN; kc += 16) {
        {   // A: cw[co][ci] -> As[k][co]  (transpose on store)
            int co = t & 63, kk = (t >> 6) * 8;
            float4 a0 = *(const float4*)&cw[(size_t)co * CIN + kc + kk];
            float4 a1 = *(const float4*)&cw[(size_t)co * CIN + kc + kk + 4];
            As[kk + 0][co] = a0.x; As[kk + 1][co] = a0.y;
            As[kk + 2][co] = a0.z; As[kk + 3][co] = a0.w;
            As[kk + 4][co] = a1.x; As[kk + 5][co] = a1.y;
            As[kk + 6][co] = a1.z; As[kk + 7][co] = a1.w;
        }
        {   // B: X[k][n] -> Bs[k][n]  (16k x 32n = 512 elems, 4/thread)
            int kk = t >> 3, nn = (t & 7) * 4;
            float4 b0 = *(const float4*)&Xb[(size_t)(kc + kk) * HWHW + n_base + nn];
            *(float4*)&Bs[kk][nn] = b0;
        }
        __syncthreads();
        #pragma unroll
        for (int k = 0; k < 16; ++k) {
            ulonglong2 aLo = *(const ulonglong2*)&As[k][co0];       // pairs 0,1
            ulonglong2 aHi = *(const ulonglong2*)&As[k][co0 + 4];   // pairs 2,3
            float2 bv = *(const float2*)&Bs[k][n0];
            u64 bd0 = dup2(bv.x), bd1 = dup2(bv.y);
            fma2(acc[0][0], aLo.x, bd0); fma2(acc[0][1], aLo.x, bd1);
            fma2(acc[1][0], aLo.y, bd0); fma2(acc[1][1], aLo.y, bd1);
            fma2(acc[2][0], aHi.x, bd0); fma2(acc[2][1], aHi.x, bd1);
            fma2(acc[3][0], aHi.y, bd0); fma2(acc[3][1], aHi.y, bd1);
        }
        __syncthreads();
    }
    float val[8][2];
    #pragma unroll
    for (int p = 0; p < 4; ++p)
        #pragma unroll
        for (int nj = 0; nj < 2; ++nj) {
            float2 f = unpack2(acc[p][nj]);
            val[2 * p][nj] = f.x; val[2 * p + 1][nj] = f.y;
        }
    #pragma unroll
    for (int i = 0; i < 8; ++i) {
        int co = co0 + i;
        float sc = gamma[co] * rsqrtf(var[co] + 1e-5f);
        float sh = beta[co] - mean[co] * sc;
        float2 v;
        v.x = fmaxf(val[i][0] * sc + sh, 0.f);
        v.y = fmaxf(val[i][1] * sc + sh, 0.f);
        *(float2*)&g_W1[((size_t)b * CMID + co) * HWHW + n_base + n0] = v;
    }
}

// ---------------------------------------------------------------------------
// K2: 3x3 conv (64ci -> 100co, pad 1) + BN (no relu)
// block: 32x8 spatial tile, 256 thr = 32 cols x 8 rows, thread = 1 px x 8 co.
// grid (16, 13, 2) = 416 blocks x 8 warps = 22 warps/SM.
// per (ci,k): 1 LDS.32 + 1 dup + 2 W LDS.128(bcast) + 4 FFMA2
// ---------------------------------------------------------------------------
__global__ __launch_bounds__(256) void k2_conv3x3(
    const float* __restrict__ ew,
    const float* __restrict__ gamma, const float* __restrict__ beta,
    const float* __restrict__ mean, const float* __restrict__ var)
{
    __shared__ float Xs[16][10][36];               // [ci][row][col], 34 used
    __shared__ __align__(16) float Ws2[16][9][8];  // [ci][k][co]
    int b = blockIdx.z;
    int co0 = blockIdx.y * 8;
    int tx0 = (blockIdx.x & 1) * 32;
    int ty0 = (blockIdx.x >> 1) * 8;
    int t = threadIdx.x;
    int tx = t & 31, ty = t >> 5;                  // 1 px per thread

    // staging map: thread = (ci = t>>4, col lane sq = t&15): cols sq+16m
    int sc_ = t >> 4;
    int sq  = t & 15;
    int xga = tx0 + sq - 1;
    int xgb = tx0 + sq + 15;
    int xgc = tx0 + sq + 31;
    bool okxa = (xga >= 0) && (xga < 64);
    bool okxb = (xgb < 64);
    bool okxc = (sq < 2) && (xgc < 64);

    u64 acc[4] = {0ULL, 0ULL, 0ULL, 0ULL};
    for (int cic = 0; cic < 4; ++cic) {
        {   // X stage: 10 rows x 34 cols x 16 ci
            const float* basec = g_W1 +
                (((size_t)b * CMID + cic * 16 + sc_) * 64) * 64;
            #pragma unroll 2
            for (int r = 0; r < 10; ++r) {
                int y = ty0 + r - 1;
                bool oky = (y >= 0) && (y < 64);
                const float* src = basec + (size_t)y * 64;
                float va = (oky && okxa) ? src[xga] : 0.f;
                float vb = (oky && okxb) ? src[xgb] : 0.f;
                float vc = (oky && okxc) ? src[xgc] : 0.f;
                float* dst = &Xs[sc_][r][0];
                dst[sq] = va;
                dst[sq + 16] = vb;
                if (sq < 2) dst[sq + 32] = vc;
            }
        }
        // W stage: 16ci x 9k x 8co = 1152, guard ragged co
        for (int e = t; e < 1152; e += 256) {
            int co = e & 7, rem = e >> 3;
            int k = rem % 9, ci = rem / 9;
            int cg = co0 + co;
            float w = (cg < CENC)
                ? ew[(size_t)cg * (CMID * 9) + (cic * 16 + ci) * 9 + k] : 0.f;
            Ws2[ci][k][co] = w;
        }
        __syncthreads();
        for (int ci = 0; ci < 16; ++ci) {
            #pragma unroll
            for (int ky = 0; ky < 3; ++ky)
            #pragma unroll
            for (int kx = 0; kx < 3; ++kx) {
                float xv = Xs[ci][ty + ky][tx + kx];
                ulonglong2 wLo = *(const ulonglong2*)&Ws2[ci][ky * 3 + kx][0];
                ulonglong2 wHi = *(const ulonglong2*)&Ws2[ci][ky * 3 + kx][4];
                u64 xd = dup2(xv);
                fma2(acc[0], wLo.x, xd); fma2(acc[1], wLo.y, xd);
                fma2(acc[2], wHi.x, xd); fma2(acc[3], wHi.y, xd);
            }
        }
        __syncthreads();
    }
    float r0[8];
    #pragma unroll
    for (int q = 0; q < 4; ++q) {
        float2 f = unpack2(acc[q]); r0[2 * q] = f.x; r0[2 * q + 1] = f.y;
    }
    #pragma unroll
    for (int i = 0; i < 8; ++i) {
        int ch = co0 + i;
        if (ch < CENC) {
            float sc = gamma[ch] * rsqrtf(var[ch] + 1e-5f);
            float sh = beta[ch] - mean[ch] * sc;
            size_t base = ((size_t)b * CENC + ch) * 64;
            g_W2[(base + ty0 + ty) * 64 + tx0 + tx] = r0[i] * sc + sh;
        }
    }
}

// ---------------------------------------------------------------------------
// K3: pixel-shuffle + clamp + pow + softmax over 25 taps (BN already in K2)
// thread = (b, pixel, dydx); writes into k4-tile-permuted g_Wn
// ---------------------------------------------------------------------------
__global__ __launch_bounds__(256) void k3_weights(const float* __restrict__ power_p)
{
    int idx = blockIdx.x * 256 + threadIdx.x;   // 32768 total
    int d = idx & 3;
    int rest = idx >> 2;                        // b*4096 + hl*64 + wl
    int pix = rest & 4095, b = rest >> 12;
    int hl = pix >> 6, wl = pix & 63;
    float p = fmaxf(power_p[0], 1e-5f);
    float v[25];
    float m = -1e30f;
    #pragma unroll
    for (int k = 0; k < 25; ++k) {
        int ch = k * 4 + d;                     // pixel-shuffle channel
        float raw = g_W2[((size_t)b * CENC + ch) * HWHW + pix];
        float x = fmaxf(raw, 1e-5f);
        x = __powf(x, p);
        v[k] = x;
        m = fmaxf(m, x);
    }
    float s = 0.f;
    #pragma unroll
    for (int k = 0; k < 25; ++k) { v[k] = __expf(v[k] - m); s += v[k]; }
    float inv = 1.f / s;
    // permuted output: [b][tile][within][k][d]
    int tile   = ((hl >> 3) << 3) + (wl >> 3);
    int within = ((hl & 7) << 3) + (wl & 7);
    float* o = g_Wn + (((size_t)b * 64 + tile) * 64 + within) * 100;
    #pragma unroll
    for (int k = 0; k < 25; ++k) o[k * 4 + d] = v[k] * inv;
}

// ---------------------------------------------------------------------------
// K4: weighted 5x5 low-res gather -> 128x128 output
// block: 8x8 low-res tile x 32 channels, 256 thr = 64 spatial x 4 quads,
// thread = 8 channels (4 pairs) x 4 subpixels.  acc = 32 regs -> ~50% occ.
// per tap: 1 W LDS.128 + 2 X LDS.128 + 4 dup + 16 FFMA2
// grid (64 tiles, 8 ch-chunks-of-32, 2 b)
// ---------------------------------------------------------------------------
__global__ __launch_bounds__(256) void k4_gather(
    const float* __restrict__ X, float* __restrict__ out)
{
    __shared__ __align__(16) float Xs[12][12][36];  // [r][x][c], 32 ch
    __shared__ __align__(16) float Ws[64][25][4];   // [within][tap][subpix]
    int b = blockIdx.z;
    int c0 = blockIdx.y * 32;
    int tile = blockIdx.x;
    int ty0 = (tile >> 3) * 8;
    int tx0 = (tile & 7) * 8;
    int t = threadIdx.x;
    int sp = t & 63;                 // spatial (warp = 32 spatials)
    int j  = t >> 6;                 // channel quad 0..3 (8 ch each)
    int sx = sp & 7, sy = sp >> 3;

    // weights: linear copy of 1600 float4 (already in this block's order)
    {
        const float4* wg4 = (const float4*)g_Wn + ((size_t)b * 64 + tile) * 1600;
        float4* wsm = (float4*)&Ws[0][0][0];
        #pragma unroll
        for (int e = t; e < 1600; e += 256) wsm[e] = wg4[e];
    }
    // X tile: positions own a fixed (r,x); pack 4 channels -> STS.128
    if (t < 144) {
        int r = t / 12, x = t % 12;
        int y = ty0 + r - 2, xg = tx0 + x - 2;
        bool ok = (y >= 0) && (y < 64) && (xg >= 0) && (xg < 64);
        const float* src = X + (((size_t)b * CIN + c0) * 64 + y) * 64 + xg;
        float* dst = &Xs[r][x][0];
        #pragma unroll
        for (int c = 0; c < 32; c += 4) {
            float4 v;
            v.x = ok ? src[(size_t)(c + 0) * HWHW] : 0.f;
            v.y = ok ? src[(size_t)(c + 1) * HWHW] : 0.f;
            v.z = ok ? src[(size_t)(c + 2) * HWHW] : 0.f;
            v.w = ok ? src[(size_t)(c + 3) * HWHW] : 0.f;
            *(float4*)&dst[c] = v;
        }
    }
    __syncthreads();

    // acc[pp][dd]: channel pair pp (ch 2pp,2pp+1 of this quad) x subpix dd
    u64 acc[4][4];
    #pragma unroll
    for (int pp = 0; pp < 4; ++pp)
        #pragma unroll
        for (int dd = 0; dd < 4; ++dd) acc[pp][dd] = 0ULL;
    int cb8 = j * 8;
    #pragma unroll
    for (int k = 0; k < 25; ++k) {
        int ki = k / 5, kj = k % 5;
        const float4 w4 = *(const float4*)&Ws[sp][k][0];
        u64 wd0 = dup2(w4.x), wd1 = dup2(w4.y), wd2 = dup2(w4.z), wd3 = dup2(w4.w);
        const float* xr = &Xs[sy + ki][sx + kj][cb8];
        ulonglong2 xa = *(const ulonglong2*)&xr[0];
        ulonglong2 xb = *(const ulonglong2*)&xr[4];
        u64 xp[4] = {xa.x, xa.y, xb.x, xb.y};
        #pragma unroll
        for (int pp = 0; pp < 4; ++pp) {
            fma2(acc[pp][0], xp[pp], wd0);
            fma2(acc[pp][1], xp[pp], wd1);
            fma2(acc[pp][2], xp[pp], wd2);
            fma2(acc[pp][3], xp[pp], wd3);
        }
    }

    // unpack + store: subpix d = dy*2+dx ; float2 over dx
    int hl = ty0 + sy, wl = tx0 + sx;
    int w_ = 2 * wl;
    #pragma unroll
    for (int pp = 0; pp < 4; ++pp) {
        float a[2][4];
        #pragma unroll
        for (int dd = 0; dd < 4; ++dd) {
            float2 f = unpack2(acc[pp][dd]);
            a[0][dd] = f.x; a[1][dd] = f.y;
        }
        #pragma unroll
        for (int q = 0; q < 2; ++q) {
            int ch = c0 + cb8 + 2 * pp + q;
            size_t cbase = (((size_t)b * CIN + ch) * 128) * 128;
            *(float2*)&out[cbase + (size_t)(2 * hl)     * 128 + w_] = make_float2(a[q][0], a[q][1]);
            *(float2*)&out[cbase + (size_t)(2 * hl + 1) * 128 + w_] = make_float2(a[q][2], a[q][3]);
        }
    }
}

// ---------------------------------------------------------------------------
extern "C" void kernel_launch(void* const* d_in, const int* in_sizes, int n_in,
                              void* d_out, int out_size)
{
    const float* X          = (const float*)d_in[0];
    const float* comp_w     = (const float*)d_in[1];
    const float* comp_gamma = (const float*)d_in[2];
    const float* comp_beta  = (const float*)d_in[3];
    const float* comp_mean  = (const float*)d_in[4];
    const float* comp_var   = (const float*)d_in[5];
    const float* enc_w      = (const float*)d_in[6];
    const float* enc_gamma  = (const float*)d_in[7];
    const float* enc_beta   = (const float*)d_in[8];
    const float* enc_mean   = (const float*)d_in[9];
    const float* enc_var    = (const float*)d_in[10];
    const float* power_p    = (const float*)d_in[11];
    float* out = (float*)d_out;

    k1_conv1x1<<<dim3(128, 2), 128>>>(X, comp_w, comp_gamma, comp_beta,
                                      comp_mean, comp_var);
    k2_conv3x3<<<dim3(16, 13, 2), 256>>>(enc_w, enc_gamma, enc_beta,
                                         enc_mean, enc_var);
    k3_weights<<<128, 256>>>(power_p);
    k4_gather<<<dim3(64, 8, 2), 256>>>(X, out);
}

// round 16
// speedup vs baseline: 1.9725x; 1.9725x over previous
#include <cuda_runtime.h>

#define BB   2
#define CIN  256
#define CMID 64
#define CENC 100
#define HWHW 4096   // 64*64

typedef unsigned long long u64;

// ---- packed fp32x2 helpers (FFMA2: one instr = two fp32 FMAs, full precision)
__device__ __forceinline__ u64 dup2(float v) {
    u64 r; asm("mov.b64 %0, {%1,%1};" : "=l"(r) : "f"(v)); return r;
}
__device__ __forceinline__ void fma2(u64& d, u64 a, u64 b) {
    asm("fma.rn.f32x2 %0, %1, %2, %0;" : "+l"(d) : "l"(a), "l"(b));
}
__device__ __forceinline__ void add2(u64& d, u64 a) {
    asm("add.rn.f32x2 %0, %0, %1;" : "+l"(d) : "l"(a));
}
__device__ __forceinline__ float2 unpack2(u64 v) {
    float2 f; asm("mov.b64 {%0,%1}, %2;" : "=f"(f.x), "=f"(f.y) : "l"(v)); return f;
}

// Scratch (allocation-free rule: __device__ globals)
__device__ float g_W1[BB * CMID * HWHW];        // conv1 output (b,64,64,64)
__device__ float g_W2[BB * CENC * HWHW];        // conv2 output (b,100,64,64)
// softmaxed weights permuted to k4's tile order: [b][tile(64)][within(64)][k(25)][d(4)]
__device__ float g_Wn[BB * 64 * 64 * 100];

// ---------------------------------------------------------------------------
// K1: 1x1 conv (GEMM M=64co x K=256ci x N=4096hw) + BN + ReLU   [R12 exact]
// block: 64co x 64n, 128 threads, thread = 8co (4 co-pairs) x 4n, k-chunk 16
// ---------------------------------------------------------------------------
__global__ __launch_bounds__(128) void k1_conv1x1(
    const float* __restrict__ X, const float* __restrict__ cw,
    const float* __restrict__ gamma, const float* __restrict__ beta,
    const float* __restrict__ mean, const float* __restrict__ var)
{
    __shared__ __align__(16) float As[16][68];   // [k][co]
    __shared__ __align__(16) float Bs[16][72];   // [k][n]
    int b = blockIdx.y;
    int n_base = blockIdx.x * 64;
    int t = threadIdx.x;
    int co0 = (t & 7) * 8;
    int n0  = (t >> 3) * 4;
    const float* Xb = X + (size_t)b * CIN * HWHW;
    u64 acc[4][4];                               // [co-pair][n]
    #pragma unroll
    for (int p = 0; p < 4; ++p)
        #pragma unroll
        for (int nj = 0; nj < 4; ++nj) acc[p][nj] = 0ULL;

    for (int kc = 0; kc < CIN; kc += 16) {
        {   // A: cw[co][ci] -> As[k][co]  (transpose on store)
            int co = t & 63, kk = (t >> 6) * 8;
            float4 a0 = *(const float4*)&cw[(size_t)co * CIN + kc + kk];
            float4 a1 = *(const float4*)&cw[(size_t)co * CIN + kc + kk + 4];
            As[kk + 0][co] = a0.x; As[kk + 1][co] = a0.y;
            As[kk + 2][co] = a0.z; As[kk + 3][co] = a0.w;
            As[kk + 4][co] = a1.x; As[kk + 5][co] = a1.y;
            As[kk + 6][co] = a1.z; As[kk + 7][co] = a1.w;
        }
        {   // B: X[k][n] -> Bs[k][n]
            int kk = t >> 3, nn = (t & 7) * 8;
            float4 b0 = *(const float4*)&Xb[(size_t)(kc + kk) * HWHW + n_base + nn];
            float4 b1 = *(const float4*)&Xb[(size_t)(kc + kk) * HWHW + n_base + nn + 4];
            *(float4*)&Bs[kk][nn] = b0;
            *(float4*)&Bs[kk][nn + 4] = b1;
        }
        __syncthreads();
        #pragma unroll
        for (int k = 0; k < 16; ++k) {
            ulonglong2 aLo = *(const ulonglong2*)&As[k][co0];       // pairs 0,1
            ulonglong2 aHi = *(const ulonglong2*)&As[k][co0 + 4];   // pairs 2,3
            float4 bv = *(const float4*)&Bs[k][n0];
            u64 bd0 = dup2(bv.x), bd1 = dup2(bv.y), bd2 = dup2(bv.z), bd3 = dup2(bv.w);
            fma2(acc[0][0], aLo.x, bd0); fma2(acc[0][1], aLo.x, bd1);
            fma2(acc[0][2], aLo.x, bd2); fma2(acc[0][3], aLo.x, bd3);
            fma2(acc[1][0], aLo.y, bd0); fma2(acc[1][1], aLo.y, bd1);
            fma2(acc[1][2], aLo.y, bd2); fma2(acc[1][3], aLo.y, bd3);
            fma2(acc[2][0], aHi.x, bd0); fma2(acc[2][1], aHi.x, bd1);
            fma2(acc[2][2], aHi.x, bd2); fma2(acc[2][3], aHi.x, bd3);
            fma2(acc[3][0], aHi.y, bd0); fma2(acc[3][1], aHi.y, bd1);
            fma2(acc[3][2], aHi.y, bd2); fma2(acc[3][3], aHi.y, bd3);
        }
        __syncthreads();
    }
    float val[8][4];
    #pragma unroll
    for (int p = 0; p < 4; ++p)
        #pragma unroll
        for (int nj = 0; nj < 4; ++nj) {
            float2 f = unpack2(acc[p][nj]);
            val[2 * p][nj] = f.x; val[2 * p + 1][nj] = f.y;
        }
    #pragma unroll
    for (int i = 0; i < 8; ++i) {
        int co = co0 + i;
        float sc = gamma[co] * rsqrtf(var[co] + 1e-5f);
        float sh = beta[co] - mean[co] * sc;
        float4 v;
        v.x = fmaxf(val[i][0] * sc + sh, 0.f);
        v.y = fmaxf(val[i][1] * sc + sh, 0.f);
        v.z = fmaxf(val[i][2] * sc + sh, 0.f);
        v.w = fmaxf(val[i][3] * sc + sh, 0.f);
        *(float4*)&g_W1[((size_t)b * CMID + co) * HWHW + n_base + n0] = v;
    }
}

// ---------------------------------------------------------------------------
// K2: 3x3 conv (64ci -> 100co, pad 1) + BN (no relu)   [R12 exact]
// block: 32x8 spatial tile, 128 thr, thread = 2 rows (ty, ty+4) x 8 co
// ---------------------------------------------------------------------------
__global__ __launch_bounds__(128) void k2_conv3x3(
    const float* __restrict__ ew,
    const float* __restrict__ gamma, const float* __restrict__ beta,
    const float* __restrict__ mean, const float* __restrict__ var)
{
    __shared__ float Xs[16][10][36];               // [ci][row][col], 34 used
    __shared__ __align__(16) float Ws2[16][9][8];  // [ci][k][co]
    int b = blockIdx.z;
    int co0 = blockIdx.y * 8;
    int tx0 = (blockIdx.x & 1) * 32;
    int ty0 = (blockIdx.x >> 1) * 8;
    int t = threadIdx.x;
    int tx = t & 31, ty = t >> 5;                  // ty 0..3, rows ty, ty+4

    // staging map: thread = (ci = t>>3, col lane sq = t&7): cols sq+8m, m=0..4
    int sc_ = t >> 3;
    int sq  = t & 7;
    int xg[5]; bool okx[5];
    #pragma unroll
    for (int m = 0; m < 5; ++m) {
        int col = sq + 8 * m;
        xg[m] = tx0 + col - 1;
        okx[m] = (col < 34) && (xg[m] >= 0) && (xg[m] < 64);
    }

    u64 acc0[4] = {0ULL, 0ULL, 0ULL, 0ULL};
    u64 acc1[4] = {0ULL, 0ULL, 0ULL, 0ULL};
    for (int cic = 0; cic < 4; ++cic) {
        {   // X stage: 10 rows
            const float* basec = g_W1 +
                (((size_t)b * CMID + cic * 16 + sc_) * 64) * 64;
            #pragma unroll 2
            for (int r = 0; r < 10; ++r) {
                int y = ty0 + r - 1;
                bool oky = (y >= 0) && (y < 64);
                const float* src = basec + (size_t)y * 64;
                float* dst = &Xs[sc_][r][0];
                #pragma unroll
                for (int m = 0; m < 5; ++m) {
                    int col = sq + 8 * m;
                    float v = (oky && okx[m]) ? src[xg[m]] : 0.f;
                    if (col < 34) dst[col] = v;
                }
            }
        }
        // W stage: 16ci x 9k x 8co = 1152, guard ragged co
        for (int e = t; e < 1152; e += 128) {
            int co = e & 7, rem = e >> 3;
            int k = rem % 9, ci = rem / 9;
            int cg = co0 + co;
            float w = (cg < CENC)
                ? ew[(size_t)cg * (CMID * 9) + (cic * 16 + ci) * 9 + k] : 0.f;
            Ws2[ci][k][co] = w;
        }
        __syncthreads();
        for (int ci = 0; ci < 16; ++ci) {
            #pragma unroll
            for (int ky = 0; ky < 3; ++ky)
            #pragma unroll
            for (int kx = 0; kx < 3; ++kx) {
                float xv0 = Xs[ci][ty + ky][tx + kx];
                float xv1 = Xs[ci][ty + 4 + ky][tx + kx];
                ulonglong2 wLo = *(const ulonglong2*)&Ws2[ci][ky * 3 + kx][0];
                ulonglong2 wHi = *(const ulonglong2*)&Ws2[ci][ky * 3 + kx][4];
                u64 x0d = dup2(xv0), x1d = dup2(xv1);
                fma2(acc0[0], wLo.x, x0d); fma2(acc0[1], wLo.y, x0d);
                fma2(acc0[2], wHi.x, x0d); fma2(acc0[3], wHi.y, x0d);
                fma2(acc1[0], wLo.x, x1d); fma2(acc1[1], wLo.y, x1d);
                fma2(acc1[2], wHi.x, x1d); fma2(acc1[3], wHi.y, x1d);
            }
        }
        __syncthreads();
    }
    float r0[8], r1[8];
    #pragma unroll
    for (int q = 0; q < 4; ++q) {
        float2 f0 = unpack2(acc0[q]); r0[2 * q] = f0.x; r0[2 * q + 1] = f0.y;
        float2 f1 = unpack2(acc1[q]); r1[2 * q] = f1.x; r1[2 * q + 1] = f1.y;
    }
    #pragma unroll
    for (int i = 0; i < 8; ++i) {
        int ch = co0 + i;
        if (ch < CENC) {
            float sc = gamma[ch] * rsqrtf(var[ch] + 1e-5f);
            float sh = beta[ch] - mean[ch] * sc;
            size_t base = ((size_t)b * CENC + ch) * 64;
            g_W2[(base + ty0 + ty) * 64 + tx0 + tx]     = r0[i] * sc + sh;
            g_W2[(base + ty0 + ty + 4) * 64 + tx0 + tx] = r1[i] * sc + sh;
        }
    }
}

// ---------------------------------------------------------------------------
// K3: pixel-shuffle + clamp + pow + softmax over 25 taps   [R12 exact]
// ---------------------------------------------------------------------------
__global__ __launch_bounds__(256) void k3_weights(const float* __restrict__ power_p)
{
    int idx = blockIdx.x * 256 + threadIdx.x;   // 32768 total
    int d = idx & 3;
    int rest = idx >> 2;                        // b*4096 + hl*64 + wl
    int pix = rest & 4095, b = rest >> 12;
    int hl = pix >> 6, wl = pix & 63;
    float p = fmaxf(power_p[0], 1e-5f);
    float v[25];
    float m = -1e30f;
    #pragma unroll
    for (int k = 0; k < 25; ++k) {
        int ch = k * 4 + d;                     // pixel-shuffle channel
        float raw = g_W2[((size_t)b * CENC + ch) * HWHW + pix];
        float x = fmaxf(raw, 1e-5f);
        x = __powf(x, p);
        v[k] = x;
        m = fmaxf(m, x);
    }
    float s = 0.f;
    #pragma unroll
    for (int k = 0; k < 25; ++k) { v[k] = __expf(v[k] - m); s += v[k]; }
    float inv = 1.f / s;
    // permuted output: [b][tile][within][k][d]
    int tile   = ((hl >> 3) << 3) + (wl >> 3);
    int within = ((hl & 7) << 3) + (wl & 7);
    float* o = g_Wn + (((size_t)b * 64 + tile) * 64 + within) * 100;
    #pragma unroll
    for (int k = 0; k < 25; ++k) o[k * 4 + d] = v[k] * inv;
}

// ---------------------------------------------------------------------------
// K4: weighted 5x5 low-res gather -> 128x128 output  [tap-split version]
// block: 8x8 low-res tile x 16 channels, 256 thr =
//        64 spatial x 2 ch-quads(8ch) x 2 TAP-HALVES (taps 0-12 / 13-24).
// acc = 16 u64 (~60 regs) -> 32 warps/SM; f32x2 smem reduction merges halves.
// grid (64 tiles, 16 ch-chunks-of-16, 2 b)
// ---------------------------------------------------------------------------
__global__ __launch_bounds__(256) void k4_gather(
    const float* __restrict__ X, float* __restrict__ out)
{
    __shared__ __align__(16) float Xs[12][12][20];  // [r][x][c], 16 ch used
    __shared__ __align__(16) float Ws[64][25][4];   // [within][tap][subpix]
    __shared__ __align__(16) u64 Red[128][18];      // reduction, padded stride
    int b = blockIdx.z;
    int c0 = blockIdx.y * 16;
    int tile = blockIdx.x;
    int ty0 = (tile >> 3) * 8;
    int tx0 = (tile & 7) * 8;
    int t = threadIdx.x;
    int sp  = t & 63;                // spatial
    int j   = t >> 6;                // 0..3
    int chq = j & 1;                 // channel quad (8 ch)
    int g   = j >> 1;                // tap half
    int sx = sp & 7, sy = sp >> 3;

    // weights: linear copy of 1600 float4 (already in this block's order)
    {
        const float4* wg4 = (const float4*)g_Wn + ((size_t)b * 64 + tile) * 1600;
        float4* wsm = (float4*)&Ws[0][0][0];
        for (int e = t; e < 1600; e += 256) wsm[e] = wg4[e];
    }
    // X tile: positions own a fixed (r,x); 16 channels, float4-packed stores
    if (t < 144) {
        int r = t / 12, x = t % 12;
        int y = ty0 + r - 2, xg = tx0 + x - 2;
        bool ok = (y >= 0) && (y < 64) && (xg >= 0) && (xg < 64);
        const float* src = X + (((size_t)b * CIN + c0) * 64 + y) * 64 + xg;
        float* dst = &Xs[r][x][0];
        #pragma unroll
        for (int c = 0; c < 16; c += 4) {
            float4 v;
            v.x = ok ? src[(size_t)(c + 0) * HWHW] : 0.f;
            v.y = ok ? src[(size_t)(c + 1) * HWHW] : 0.f;
            v.z = ok ? src[(size_t)(c + 2) * HWHW] : 0.f;
            v.w = ok ? src[(size_t)(c + 3) * HWHW] : 0.f;
            *(float4*)&dst[c] = v;
        }
    }
    __syncthreads();

    // acc[pp][dd]: channel pair pp (ch 2pp,2pp+1 of this quad) x subpix dd
    u64 acc[4][4];
    #pragma unroll
    for (int pp = 0; pp < 4; ++pp)
        #pragma unroll
        for (int dd = 0; dd < 4; ++dd) acc[pp][dd] = 0ULL;
    int cb8 = chq * 8;

    if (g == 0) {
        #pragma unroll
        for (int k = 0; k < 13; ++k) {
            int ki = k / 5, kj = k % 5;
            const float4 w4 = *(const float4*)&Ws[sp][k][0];
            u64 wd0 = dup2(w4.x), wd1 = dup2(w4.y), wd2 = dup2(w4.z), wd3 = dup2(w4.w);
            const float* xr = &Xs[sy + ki][sx + kj][cb8];
            ulonglong2 xa = *(const ulonglong2*)&xr[0];
            ulonglong2 xb = *(const ulonglong2*)&xr[4];
            u64 xp[4] = {xa.x, xa.y, xb.x, xb.y};
            #pragma unroll
            for (int pp = 0; pp < 4; ++pp) {
                fma2(acc[pp][0], xp[pp], wd0);
                fma2(acc[pp][1], xp[pp], wd1);
                fma2(acc[pp][2], xp[pp], wd2);
                fma2(acc[pp][3], xp[pp], wd3);
            }
        }
    } else {
        #pragma unroll
        for (int k = 13; k < 25; ++k) {
            int ki = k / 5, kj = k % 5;
            const float4 w4 = *(const float4*)&Ws[sp][k][0];
            u64 wd0 = dup2(w4.x), wd1 = dup2(w4.y), wd2 = dup2(w4.z), wd3 = dup2(w4.w);
            const float* xr = &Xs[sy + ki][sx + kj][cb8];
            ulonglong2 xa = *(const ulonglong2*)&xr[0];
            ulonglong2 xb = *(const ulonglong2*)&xr[4];
            u64 xp[4] = {xa.x, xa.y, xb.x, xb.y};
            #pragma unroll
            for (int pp = 0; pp < 4; ++pp) {
                fma2(acc[pp][0], xp[pp], wd0);
                fma2(acc[pp][1], xp[pp], wd1);
                fma2(acc[pp][2], xp[pp], wd2);
                fma2(acc[pp][3], xp[pp], wd3);
            }
        }
        // publish upper-half partials
        u64* rrow = &Red[chq * 64 + sp][0];
        #pragma unroll
        for (int pp = 0; pp < 4; ++pp)
            #pragma unroll
            for (int dd = 0; dd < 4; ++dd)
                rrow[pp * 4 + dd] = acc[pp][dd];
    }
    __syncthreads();

    if (g == 0) {
        // merge halves (packed fp32x2 adds), then unpack + store
        const u64* rrow = &Red[chq * 64 + sp][0];
        #pragma unroll
        for (int pp = 0; pp < 4; ++pp)
            #pragma unroll
            for (int dd = 0; dd < 4; ++dd)
                add2(acc[pp][dd], rrow[pp * 4 + dd]);

        int hl = ty0 + sy, wl = tx0 + sx;
        int w_ = 2 * wl;
        #pragma unroll
        for (int pp = 0; pp < 4; ++pp) {
            float a[2][4];
            #pragma unroll
            for (int dd = 0; dd < 4; ++dd) {
                float2 f = unpack2(acc[pp][dd]);
                a[0][dd] = f.x; a[1][dd] = f.y;
            }
            #pragma unroll
            for (int q = 0; q < 2; ++q) {
                int ch = c0 + cb8 + 2 * pp + q;
                size_t cbase = (((size_t)b * CIN + ch) * 128) * 128;
                *(float2*)&out[cbase + (size_t)(2 * hl)     * 128 + w_] = make_float2(a[q][0], a[q][1]);
                *(float2*)&out[cbase + (size_t)(2 * hl + 1) * 128 + w_] = make_float2(a[q][2], a[q][3]);
            }
        }
    }
}

// ---------------------------------------------------------------------------
extern "C" void kernel_launch(void* const* d_in, const int* in_sizes, int n_in,
                              void* d_out, int out_size)
{
    const float* X          = (const float*)d_in[0];
    const float* comp_w     = (const float*)d_in[1];
    const float* comp_gamma = (const float*)d_in[2];
    const float* comp_beta  = (const float*)d_in[3];
    const float* comp_mean  = (const float*)d_in[4];
    const float* comp_var   = (const float*)d_in[5];
    const float* enc_w      = (const float*)d_in[6];
    const float* enc_gamma  = (const float*)d_in[7];
    const float* enc_beta   = (const float*)d_in[8];
    const float* enc_mean   = (const float*)d_in[9];
    const float* enc_var    = (const float*)d_in[10];
    const float* power_p    = (const float*)d_in[11];
    float* out = (float*)d_out;

    k1_conv1x1<<<dim3(64, 2), 128>>>(X, comp_w, comp_gamma, comp_beta,
                                     comp_mean, comp_var);
    k2_conv3x3<<<dim3(16, 13, 2), 128>>>(enc_w, enc_gamma, enc_beta,
                                         enc_mean, enc_var);
    k3_weights<<<128, 256>>>(power_p);
    k4_gather<<<dim3(64, 16, 2), 256>>>(X, out);
}

// round 17
// speedup vs baseline: 1.9820x; 1.0048x over previous
#include <cuda_runtime.h>

#define BB   2
#define CIN  256
#define CMID 64
#define CENC 100
#define HWHW 4096   // 64*64

typedef unsigned long long u64;

// ---- packed fp32x2 helpers (FFMA2: one instr = two fp32 FMAs, full precision)
__device__ __forceinline__ u64 dup2(float v) {
    u64 r; asm("mov.b64 %0, {%1,%1};" : "=l"(r) : "f"(v)); return r;
}
__device__ __forceinline__ void fma2(u64& d, u64 a, u64 b) {
    asm("fma.rn.f32x2 %0, %1, %2, %0;" : "+l"(d) : "l"(a), "l"(b));
}
__device__ __forceinline__ float2 unpack2(u64 v) {
    float2 f; asm("mov.b64 {%0,%1}, %2;" : "=f"(f.x), "=f"(f.y) : "l"(v)); return f;
}

// Scratch (allocation-free rule: __device__ globals)
// g_W1p: conv1 output with zero border, [b*64+c][66 rows][72 cols],
//        data at [1+y][4+x]. Border is NEVER written -> stays .bss zero.
__device__ float g_W1p[BB * CMID * 66 * 72];
__device__ float g_W2[BB * CENC * HWHW];        // conv2 output (b,100,64,64)
// softmaxed weights permuted to k4's tile order: [b][tile(64)][within(64)][k(25)][d(4)]
__device__ float g_Wn[BB * 64 * 64 * 100];

// ---------------------------------------------------------------------------
// K1: 1x1 conv (GEMM M=64co x K=256ci x N=4096hw) + BN + ReLU   [R12 compute]
// block: 64co x 64n, 128 threads, thread = 8co (4 co-pairs) x 4n, k-chunk 16
// Output goes to padded g_W1p (only store indexing changed vs R12).
// ---------------------------------------------------------------------------
__global__ __launch_bounds__(128) void k1_conv1x1(
    const float* __restrict__ X, const float* __restrict__ cw,
    const float* __restrict__ gamma, const float* __restrict__ beta,
    const float* __restrict__ mean, const float* __restrict__ var)
{
    __shared__ __align__(16) float As[16][68];   // [k][co]
    __shared__ __align__(16) float Bs[16][72];   // [k][n]
    int b = blockIdx.y;
    int n_base = blockIdx.x * 64;
    int t = threadIdx.x;
    int co0 = (t & 7) * 8;
    int n0  = (t >> 3) * 4;
    const float* Xb = X + (size_t)b * CIN * HWHW;
    u64 acc[4][4];                               // [co-pair][n]
    #pragma unroll
    for (int p = 0; p < 4; ++p)
        #pragma unroll
        for (int nj = 0; nj < 4; ++nj) acc[p][nj] = 0ULL;

    for (int kc = 0; kc < CIN; kc += 16) {
        {   // A: cw[co][ci] -> As[k][co]  (transpose on store)
            int co = t & 63, kk = (t >> 6) * 8;
            float4 a0 = *(const float4*)&cw[(size_t)co * CIN + kc + kk];
            float4 a1 = *(const float4*)&cw[(size_t)co * CIN + kc + kk + 4];
            As[kk + 0][co] = a0.x; As[kk + 1][co] = a0.y;
            As[kk + 2][co] = a0.z; As[kk + 3][co] = a0.w;
            As[kk + 4][co] = a1.x; As[kk + 5][co] = a1.y;
            As[kk + 6][co] = a1.z; As[kk + 7][co] = a1.w;
        }
        {   // B: X[k][n] -> Bs[k][n]
            int kk = t >> 3, nn = (t & 7) * 8;
            float4 b0 = *(const float4*)&Xb[(size_t)(kc + kk) * HWHW + n_base + nn];
            float4 b1 = *(const float4*)&Xb[(size_t)(kc + kk) * HWHW + n_base + nn + 4];
            *(float4*)&Bs[kk][nn] = b0;
            *(float4*)&Bs[kk][nn + 4] = b1;
        }
        __syncthreads();
        #pragma unroll
        for (int k = 0; k < 16; ++k) {
            ulonglong2 aLo = *(const ulonglong2*)&As[k][co0];       // pairs 0,1
            ulonglong2 aHi = *(const ulonglong2*)&As[k][co0 + 4];   // pairs 2,3
            float4 bv = *(const float4*)&Bs[k][n0];
            u64 bd0 = dup2(bv.x), bd1 = dup2(bv.y), bd2 = dup2(bv.z), bd3 = dup2(bv.w);
            fma2(acc[0][0], aLo.x, bd0); fma2(acc[0][1], aLo.x, bd1);
            fma2(acc[0][2], aLo.x, bd2); fma2(acc[0][3], aLo.x, bd3);
            fma2(acc[1][0], aLo.y, bd0); fma2(acc[1][1], aLo.y, bd1);
            fma2(acc[1][2], aLo.y, bd2); fma2(acc[1][3], aLo.y, bd3);
            fma2(acc[2][0], aHi.x, bd0); fma2(acc[2][1], aHi.x, bd1);
            fma2(acc[2][2], aHi.x, bd2); fma2(acc[2][3], aHi.x, bd3);
            fma2(acc[3][0], aHi.y, bd0); fma2(acc[3][1], aHi.y, bd1);
            fma2(acc[3][2], aHi.y, bd2); fma2(acc[3][3], aHi.y, bd3);
        }
        __syncthreads();
    }
    float val[8][4];
    #pragma unroll
    for (int p = 0; p < 4; ++p)
        #pragma unroll
        for (int nj = 0; nj < 4; ++nj) {
            float2 f = unpack2(acc[p][nj]);
            val[2 * p][nj] = f.x; val[2 * p + 1][nj] = f.y;
        }
    int n = n_base + n0;
    int row = n >> 6, col = n & 63;              // float4 never crosses a row
    #pragma unroll
    for (int i = 0; i < 8; ++i) {
        int co = co0 + i;
        float sc = gamma[co] * rsqrtf(var[co] + 1e-5f);
        float sh = beta[co] - mean[co] * sc;
        float4 v;
        v.x = fmaxf(val[i][0] * sc + sh, 0.f);
        v.y = fmaxf(val[i][1] * sc + sh, 0.f);
        v.z = fmaxf(val[i][2] * sc + sh, 0.f);
        v.w = fmaxf(val[i][3] * sc + sh, 0.f);
        *(float4*)&g_W1p[((size_t)(b * CMID + co) * 66 + row + 1) * 72 + 4 + col] = v;
    }
}

// ---------------------------------------------------------------------------
// K2 staging helper: cp.async one 8-ci chunk (8 x 10 rows x 40 cols) into smem
// ---------------------------------------------------------------------------
__device__ __forceinline__ void k2_stage_chunk(
    int t, const float* __restrict__ Pbase, int cic, int ty0, int tx0,
    float* dstbase)
{
    #pragma unroll
    for (int i = 0; i < 7; ++i) {
        int e = t + 128 * i;
        if (e < 800) {
            int ci_l = e / 100, rem = e % 100;
            int r = rem / 10, q = rem % 10;
            const float* src = Pbase +
                ((size_t)(cic * 8 + ci_l) * 66 + ty0 + r) * 72 + tx0 + q * 4;
            unsigned dst = (unsigned)__cvta_generic_to_shared(
                dstbase + (ci_l * 10 + r) * 40 + q * 4);
            asm volatile("cp.async.ca.shared.global [%0], [%1], 16;"
                         :: "r"(dst), "l"(src) : "memory");
        }
    }
    asm volatile("cp.async.commit_group;" ::: "memory");
}

// ---------------------------------------------------------------------------
// K2: 3x3 conv (64ci -> 100co, pad 1) + BN (no relu)
// Same compute shape as R12 (32x8 tile, 128 thr, 2 rows x 8 co / thread).
// NEW: zero-padded input (no bounds checks), all-ci weights staged once,
// cp.async double-buffered X pipeline over 8 chunks of 8 ci.
// ---------------------------------------------------------------------------
__global__ __launch_bounds__(128) void k2_conv3x3(
    const float* __restrict__ ew,
    const float* __restrict__ gamma, const float* __restrict__ beta,
    const float* __restrict__ mean, const float* __restrict__ var)
{
    __shared__ __align__(16) float Xs[2][8][10][40];   // 25.6 KB
    __shared__ __align__(16) float Ws2[64][9][8];      // [ci][k][co] 18.4 KB
    int b = blockIdx.z;
    int co0 = blockIdx.y * 8;
    int tx0 = (blockIdx.x & 1) * 32;
    int ty0 = (blockIdx.x >> 1) * 8;
    int t = threadIdx.x;
    int tx = t & 31, ty = t >> 5;                  // ty 0..3, rows ty, ty+4

    // W stage once: 64ci x 9k x 8co = 4608 (ragged co zero-filled)
    for (int e = t; e < 4608; e += 128) {
        int co = e & 7, rem = e >> 3;
        int k = rem % 9, ci = rem / 9;
        int cg = co0 + co;
        Ws2[ci][k][co] = (cg < CENC)
            ? ew[(size_t)cg * (CMID * 9) + ci * 9 + k] : 0.f;
    }

    const float* Pbase = g_W1p + (size_t)b * CMID * 66 * 72;
    k2_stage_chunk(t, Pbase, 0, ty0, tx0, &Xs[0][0][0][0]);
    k2_stage_chunk(t, Pbase, 1, ty0, tx0, &Xs[1][0][0][0]);

    u64 acc0[4] = {0ULL, 0ULL, 0ULL, 0ULL};
    u64 acc1[4] = {0ULL, 0ULL, 0ULL, 0ULL};
    for (int cic = 0; cic < 8; ++cic) {
        if (cic < 7) asm volatile("cp.async.wait_group 1;" ::: "memory");
        else         asm volatile("cp.async.wait_group 0;" ::: "memory");
        __syncthreads();
        int buf = cic & 1;
        #pragma unroll 2
        for (int ci = 0; ci < 8; ++ci) {
            int cig = cic * 8 + ci;
            #pragma unroll
            for (int ky = 0; ky < 3; ++ky)
            #pragma unroll
            for (int kx = 0; kx < 3; ++kx) {
                float xv0 = Xs[buf][ci][ty + ky][3 + tx + kx];
                float xv1 = Xs[buf][ci][ty + 4 + ky][3 + tx + kx];
                ulonglong2 wLo = *(const ulonglong2*)&Ws2[cig][ky * 3 + kx][0];
                ulonglong2 wHi = *(const ulonglong2*)&Ws2[cig][ky * 3 + kx][4];
                u64 x0d = dup2(xv0), x1d = dup2(xv1);
                fma2(acc0[0], wLo.x, x0d); fma2(acc0[1], wLo.y, x0d);
                fma2(acc0[2], wHi.x, x0d); fma2(acc0[3], wHi.y, x0d);
                fma2(acc1[0], wLo.x, x1d); fma2(acc1[1], wLo.y, x1d);
                fma2(acc1[2], wHi.x, x1d); fma2(acc1[3], wHi.y, x1d);
            }
        }
        __syncthreads();
        if (cic + 2 < 8)
            k2_stage_chunk(t, Pbase, cic + 2, ty0, tx0, &Xs[buf][0][0][0]);
    }

    float r0[8], r1[8];
    #pragma unroll
    for (int q = 0; q < 4; ++q) {
        float2 f0 = unpack2(acc0[q]); r0[2 * q] = f0.x; r0[2 * q + 1] = f0.y;
        float2 f1 = unpack2(acc1[q]); r1[2 * q] = f1.x; r1[2 * q + 1] = f1.y;
    }
    #pragma unroll
    for (int i = 0; i < 8; ++i) {
        int ch = co0 + i;
        if (ch < CENC) {
            float sc = gamma[ch] * rsqrtf(var[ch] + 1e-5f);
            float sh = beta[ch] - mean[ch] * sc;
            size_t base = ((size_t)b * CENC + ch) * 64;
            g_W2[(base + ty0 + ty) * 64 + tx0 + tx]     = r0[i] * sc + sh;
            g_W2[(base + ty0 + ty + 4) * 64 + tx0 + tx] = r1[i] * sc + sh;
        }
    }
}

// ---------------------------------------------------------------------------
// K3: pixel-shuffle + clamp + pow + softmax over 25 taps   [R12 exact]
// ---------------------------------------------------------------------------
__global__ __launch_bounds__(256) void k3_weights(const float* __restrict__ power_p)
{
    int idx = blockIdx.x * 256 + threadIdx.x;   // 32768 total
    int d = idx & 3;
    int rest = idx >> 2;                        // b*4096 + hl*64 + wl
    int pix = rest & 4095, b = rest >> 12;
    int hl = pix >> 6, wl = pix & 63;
    float p = fmaxf(power_p[0], 1e-5f);
    float v[25];
    float m = -1e30f;
    #pragma unroll
    for (int k = 0; k < 25; ++k) {
        int ch = k * 4 + d;                     // pixel-shuffle channel
        float raw = g_W2[((size_t)b * CENC + ch) * HWHW + pix];
        float x = fmaxf(raw, 1e-5f);
        x = __powf(x, p);
        v[k] = x;
        m = fmaxf(m, x);
    }
    float s = 0.f;
    #pragma unroll
    for (int k = 0; k < 25; ++k) { v[k] = __expf(v[k] - m); s += v[k]; }
    float inv = 1.f / s;
    // permuted output: [b][tile][within][k][d]
    int tile   = ((hl >> 3) << 3) + (wl >> 3);
    int within = ((hl & 7) << 3) + (wl & 7);
    float* o = g_Wn + (((size_t)b * 64 + tile) * 64 + within) * 100;
    #pragma unroll
    for (int k = 0; k < 25; ++k) o[k * 4 + d] = v[k] * inv;
}

// ---------------------------------------------------------------------------
// K4: weighted 5x5 low-res gather -> 128x128 output   [R12 exact, best: 23.9us]
// block: 8x8 low-res tile x 32 channels, 128 thr = 64 spatial x 2 halves,
// thread = 16 channels x 4 subpixels.
// grid (64 tiles, 8 ch-chunks-of-32, 2 b)
// ---------------------------------------------------------------------------
__global__ __launch_bounds__(128) void k4_gather(
    const float* __restrict__ X, float* __restrict__ out)
{
    __shared__ __align__(16) float Xs[12][12][36];  // [r][x][c], 32 ch
    __shared__ __align__(16) float Ws[64][25][4];   // [within][tap][subpix]
    int b = blockIdx.z;
    int c0 = blockIdx.y * 32;
    int tile = blockIdx.x;
    int ty0 = (tile >> 3) * 8;
    int tx0 = (tile & 7) * 8;
    int t = threadIdx.x;
    int sp = t & 63;                 // spatial (warp = 32 spatials)
    int j  = t >> 6;                 // channel half 0..1 (16 ch each)
    int sx = sp & 7, sy = sp >> 3;

    // weights: linear copy of 1600 float4 (already in this block's order)
    {
        const float4* wg4 = (const float4*)g_Wn + ((size_t)b * 64 + tile) * 1600;
        float4* wsm = (float4*)&Ws[0][0][0];
        for (int e = t; e < 1600; e += 128) wsm[e] = wg4[e];
    }
    // X tile: positions own a fixed (r,x); pack 4 channels -> STS.128
    for (int pos = t; pos < 144; pos += 128) {
        int r = pos / 12, x = pos % 12;
        int y = ty0 + r - 2, xg = tx0 + x - 2;
        bool ok = (y >= 0) && (y < 64) && (xg >= 0) && (xg < 64);
        const float* src = X + (((size_t)b * CIN + c0) * 64 + y) * 64 + xg;
        float* dst = &Xs[r][x][0];
        #pragma unroll
        for (int c = 0; c < 32; c += 4) {
            float4 v;
            v.x = ok ? src[(size_t)(c + 0) * HWHW] : 0.f;
            v.y = ok ? src[(size_t)(c + 1) * HWHW] : 0.f;
            v.z = ok ? src[(size_t)(c + 2) * HWHW] : 0.f;
            v.w = ok ? src[(size_t)(c + 3) * HWHW] : 0.f;
            *(float4*)&dst[c] = v;
        }
    }
    __syncthreads();

    // acc[pp][dd]: channel pair pp (ch 2pp,2pp+1 of this half) x subpix dd
    u64 acc[8][4];
    #pragma unroll
    for (int pp = 0; pp < 8; ++pp)
        #pragma unroll
        for (int dd = 0; dd < 4; ++dd) acc[pp][dd] = 0ULL;
    int cb16 = j * 16;
    #pragma unroll
    for (int k = 0; k < 25; ++k) {
        int ki = k / 5, kj = k % 5;
        const float4 w4 = *(const float4*)&Ws[sp][k][0];
        u64 wd0 = dup2(w4.x), wd1 = dup2(w4.y), wd2 = dup2(w4.z), wd3 = dup2(w4.w);
        const float* xr = &Xs[sy + ki][sx + kj][cb16];
        ulonglong2 xa = *(const ulonglong2*)&xr[0];
        ulonglong2 xb = *(const ulonglong2*)&xr[4];
        ulonglong2 xc = *(const ulonglong2*)&xr[8];
        ulonglong2 xd = *(const ulonglong2*)&xr[12];
        u64 xp[8] = {xa.x, xa.y, xb.x, xb.y, xc.x, xc.y, xd.x, xd.y};
        #pragma unroll
        for (int pp = 0; pp < 8; ++pp) {
            fma2(acc[pp][0], xp[pp], wd0);
            fma2(acc[pp][1], xp[pp], wd1);
            fma2(acc[pp][2], xp[pp], wd2);
            fma2(acc[pp][3], xp[pp], wd3);
        }
    }

    // unpack + store: subpix d = dy*2+dx ; float2 over dx
    int hl = ty0 + sy, wl = tx0 + sx;
    int w_ = 2 * wl;
    #pragma unroll
    for (int pp = 0; pp < 8; ++pp) {
        float a[2][4];
        #pragma unroll
        for (int dd = 0; dd < 4; ++dd) {
            float2 f = unpack2(acc[pp][dd]);
            a[0][dd] = f.x; a[1][dd] = f.y;
        }
        #pragma unroll
        for (int q = 0; q < 2; ++q) {
            int ch = c0 + cb16 + 2 * pp + q;
            size_t cbase = (((size_t)b * CIN + ch) * 128) * 128;
            *(float2*)&out[cbase + (size_t)(2 * hl)     * 128 + w_] = make_float2(a[q][0], a[q][1]);
            *(float2*)&out[cbase + (size_t)(2 * hl + 1) * 128 + w_] = make_float2(a[q][2], a[q][3]);
        }
    }
}

// ---------------------------------------------------------------------------
extern "C" void kernel_launch(void* const* d_in, const int* in_sizes, int n_in,
                              void* d_out, int out_size)
{
    const float* X          = (const float*)d_in[0];
    const float* comp_w     = (const float*)d_in[1];
    const float* comp_gamma = (const float*)d_in[2];
    const float* comp_beta  = (const float*)d_in[3];
    const float* comp_mean  = (const float*)d_in[4];
    const float* comp_var   = (const float*)d_in[5];
    const float* enc_w      = (const float*)d_in[6];
    const float* enc_gamma  = (const float*)d_in[7];
    const float* enc_beta   = (const float*)d_in[8];
    const float* enc_mean   = (const float*)d_in[9];
    const float* enc_var    = (const float*)d_in[10];
    const float* power_p    = (const float*)d_in[11];
    float* out = (float*)d_out;

    k1_conv1x1<<<dim3(64, 2), 128>>>(X, comp_w, comp_gamma, comp_beta,
                                     comp_mean, comp_var);
    k2_conv3x3<<<dim3(16, 13, 2), 128>>>(enc_w, enc_gamma, enc_beta,
                                         enc_mean, enc_var);
    k3_weights<<<128, 256>>>(power_p);
    k4_gather<<<dim3(64, 8, 2), 128>>>(X, out);
}